// round 2
// baseline (speedup 1.0000x reference)
#include <cuda_runtime.h>

// ---------------------------------------------------------------------------
// Policy_LSTM: 2-layer LSTM (B=512, T=1024, H=256, F_IN=10) + MLP head + softmax
//
// Design (round 1):
//   - prep kernel: repack weights once per launch into [k][j][q] interleaved
//     layout (gate q in {i,f,g,o}, unit j) so each thread's 4 gate weights at
//     a given k are one coalesced LDG.128. Combine biases. Transpose head W1.
//   - main persistent kernel: 128 CTAs x 256 threads, 4 batch rows per CTA,
//     thread j owns hidden unit j. All recurrence state in regs/SMEM. fp32
//     math using packed fma.rn.f32x2 (FFMA2). In-loop advantage head + block
//     reduction; scores written time-major to scratch.
//   - softmax kernel over the batch/time-mixed [512][1024] view.
// ---------------------------------------------------------------------------

#define BB 512
#define TT 1024
#define HH 256

// ----- device scratch (static, allocation-free) -----
__device__ float g_Wt0x[10 * 1024];     // [k<10][j][q]  from w_ih0
__device__ float g_Wt0h[256 * 1024];    // [k<256][j][q] from w_hh0
__device__ float g_Wt1[512 * 1024];     // [k<512][j][q] rows 0..255: w_ih1, 256..511: w_hh1
__device__ float g_b0[1024];            // [j][q] combined b_ih0+b_hh0
__device__ float g_b1[1024];            // [j][q] combined b_ih1+b_hh1
__device__ float g_advW1t[256 * 256];   // [k][o] = adv_w1[o][k]
__device__ float g_scores[BB * TT];     // flat time-major scores: idx = t*B + b

// ----- packed f32x2 helpers -----
typedef unsigned long long u64;

__device__ __forceinline__ u64 pk2(float lo, float hi) {
    u64 r;
    asm("mov.b64 %0, {%1, %2};" : "=l"(r) : "f"(lo), "f"(hi));
    return r;
}
__device__ __forceinline__ void upk2(u64 v, float& lo, float& hi) {
    asm("mov.b64 {%0, %1}, %2;" : "=f"(lo), "=f"(hi) : "l"(v));
}
__device__ __forceinline__ u64 ffma2(u64 a, u64 b, u64 c) {
    u64 d;
    asm("fma.rn.f32x2 %0, %1, %2, %3;" : "=l"(d) : "l"(a), "l"(b), "l"(c));
    return d;
}

// ----- fast activations (fp32, MUFU based, range-safe) -----
__device__ __forceinline__ float sigf(float v) {
    // exp(-v) -> inf for very negative v: 1/(1+inf) = 0, correct. No NaN path.
    return __fdividef(1.0f, 1.0f + __expf(-v));
}
__device__ __forceinline__ float tanhf_(float v) {
    v = fminf(fmaxf(v, -15.0f), 15.0f);   // avoid inf/inf
    float e = __expf(-2.0f * v);
    return __fdividef(1.0f - e, 1.0f + e);
}

// ---------------------------------------------------------------------------
// prep: repack weights (runs every launch; deterministic)
// ---------------------------------------------------------------------------
__global__ void __launch_bounds__(256) prep_kernel(
    const float* __restrict__ w_ih0, const float* __restrict__ w_hh0,
    const float* __restrict__ b_ih0, const float* __restrict__ b_hh0,
    const float* __restrict__ w_ih1, const float* __restrict__ w_hh1,
    const float* __restrict__ b_ih1, const float* __restrict__ b_hh1,
    const float* __restrict__ adv_w1)
{
    int idx = blockIdx.x * blockDim.x + threadIdx.x;  // grid covers 524288
    if (idx >= 512 * 1024) return;

    int k   = idx >> 10;
    int rem = idx & 1023;
    int j   = rem >> 2;
    int q   = rem & 3;
    int g   = q * 256 + j;

    g_Wt1[idx] = (k < 256) ? w_ih1[g * 256 + k] : w_hh1[g * 256 + (k - 256)];

    if (idx < 256 * 1024) g_Wt0h[idx] = w_hh0[g * 256 + k];
    if (idx < 10 * 1024)  g_Wt0x[idx] = w_ih0[g * 10 + k];
    if (idx < 1024) {
        // k == 0 here, so j,q,g decoded from idx directly
        g_b0[idx] = b_ih0[g] + b_hh0[g];
        g_b1[idx] = b_ih1[g] + b_hh1[g];
    }
    if (idx < 256 * 256) {
        int kk = idx >> 8;
        int o  = idx & 255;
        g_advW1t[idx] = adv_w1[o * 256 + kk];
    }
}

// ---------------------------------------------------------------------------
// main recurrence: 128 CTAs, 256 threads, 4 batch rows per CTA
// ---------------------------------------------------------------------------
__global__ void __launch_bounds__(256) lstm_kernel(
    const float* __restrict__ x,
    const float* __restrict__ adv_b1,
    const float* __restrict__ adv_w2,
    const float* __restrict__ adv_b2)
{
    __shared__ float4 sh1[256];       // h1: [k] -> 4 batch rows
    __shared__ float4 sh2[256];       // h2
    __shared__ float  shx[4][12];     // x_t per batch row (10 used)
    __shared__ float4 sred[8];        // per-warp reduction partials

    const int j  = threadIdx.x;       // hidden unit owned by this thread
    const int b0 = blockIdx.x * 4;    // first batch row of this CTA

    const float4* __restrict__ Wt0x = (const float4*)g_Wt0x;
    const float4* __restrict__ Wt0h = (const float4*)g_Wt0h;
    const float4* __restrict__ Wt1  = (const float4*)g_Wt1;

    const float4 bias0 = ((const float4*)g_b0)[j];
    const float4 bias1 = ((const float4*)g_b1)[j];
    const float  hb  = adv_b1[j];
    const float  w2  = adv_w2[j];
    const float  ab2 = adv_b2[0];

    float c1[4] = {0.f, 0.f, 0.f, 0.f};
    float c2[4] = {0.f, 0.f, 0.f, 0.f};
    sh1[j] = make_float4(0.f, 0.f, 0.f, 0.f);
    sh2[j] = make_float4(0.f, 0.f, 0.f, 0.f);
    __syncthreads();

    for (int t = 0; t < TT; t++) {
        // stage x_t for this CTA's 4 batch rows
        if (j < 40) {
            int r = j / 10, cc = j - r * 10;
            shx[r][cc] = x[(size_t)(b0 + r) * (TT * 10) + t * 10 + cc];
        }

        // ---------------- cell 0: gates = b0 + x W_ih0^T + h1 W_hh0^T ------
        u64 a01[4], a23[4];
        {
            u64 bi = pk2(bias0.x, bias0.y);
            u64 bg = pk2(bias0.z, bias0.w);
            #pragma unroll
            for (int r = 0; r < 4; r++) { a01[r] = bi; a23[r] = bg; }
        }
        #pragma unroll 4
        for (int k = 0; k < 256; k++) {
            float4 w4 = Wt0h[(k << 8) + j];
            u64 w01 = pk2(w4.x, w4.y);
            u64 w23 = pk2(w4.z, w4.w);
            float4 h4 = sh1[k];
            u64 p0 = pk2(h4.x, h4.x), p1 = pk2(h4.y, h4.y);
            u64 p2 = pk2(h4.z, h4.z), p3 = pk2(h4.w, h4.w);
            a01[0] = ffma2(w01, p0, a01[0]); a23[0] = ffma2(w23, p0, a23[0]);
            a01[1] = ffma2(w01, p1, a01[1]); a23[1] = ffma2(w23, p1, a23[1]);
            a01[2] = ffma2(w01, p2, a01[2]); a23[2] = ffma2(w23, p2, a23[2]);
            a01[3] = ffma2(w01, p3, a01[3]); a23[3] = ffma2(w23, p3, a23[3]);
        }
        __syncthreads();   // shx visible; everyone done reading old sh1

        #pragma unroll
        for (int k = 0; k < 10; k++) {
            float4 w4 = Wt0x[(k << 8) + j];
            u64 w01 = pk2(w4.x, w4.y);
            u64 w23 = pk2(w4.z, w4.w);
            #pragma unroll
            for (int r = 0; r < 4; r++) {
                float xv = shx[r][k];
                u64 p = pk2(xv, xv);
                a01[r] = ffma2(w01, p, a01[r]);
                a23[r] = ffma2(w23, p, a23[r]);
            }
        }

        float4 h1n;
        {
            float* h1p = (float*)&h1n;
            #pragma unroll
            for (int r = 0; r < 4; r++) {
                float gi, gf, gg, go;
                upk2(a01[r], gi, gf);
                upk2(a23[r], gg, go);
                float cn = sigf(gf) * c1[r] + sigf(gi) * tanhf_(gg);
                c1[r] = cn;
                h1p[r] = sigf(go) * tanhf_(cn);
            }
        }
        sh1[j] = h1n;        // safe: all reads of old sh1 completed pre-barrier
        __syncthreads();     // new sh1 visible

        // ---------------- cell 1: gates = b1 + h1 W_ih1^T + h2 W_hh1^T -----
        {
            u64 bi = pk2(bias1.x, bias1.y);
            u64 bg = pk2(bias1.z, bias1.w);
            #pragma unroll
            for (int r = 0; r < 4; r++) { a01[r] = bi; a23[r] = bg; }
        }
        #pragma unroll 4
        for (int k = 0; k < 256; k++) {
            float4 w4 = Wt1[(k << 8) + j];
            u64 w01 = pk2(w4.x, w4.y);
            u64 w23 = pk2(w4.z, w4.w);
            float4 h4 = sh1[k];
            u64 p0 = pk2(h4.x, h4.x), p1 = pk2(h4.y, h4.y);
            u64 p2 = pk2(h4.z, h4.z), p3 = pk2(h4.w, h4.w);
            a01[0] = ffma2(w01, p0, a01[0]); a23[0] = ffma2(w23, p0, a23[0]);
            a01[1] = ffma2(w01, p1, a01[1]); a23[1] = ffma2(w23, p1, a23[1]);
            a01[2] = ffma2(w01, p2, a01[2]); a23[2] = ffma2(w23, p2, a23[2]);
            a01[3] = ffma2(w01, p3, a01[3]); a23[3] = ffma2(w23, p3, a23[3]);
        }
        #pragma unroll 4
        for (int k = 0; k < 256; k++) {
            float4 w4 = Wt1[((k + 256) << 8) + j];
            u64 w01 = pk2(w4.x, w4.y);
            u64 w23 = pk2(w4.z, w4.w);
            float4 h4 = sh2[k];
            u64 p0 = pk2(h4.x, h4.x), p1 = pk2(h4.y, h4.y);
            u64 p2 = pk2(h4.z, h4.z), p3 = pk2(h4.w, h4.w);
            a01[0] = ffma2(w01, p0, a01[0]); a23[0] = ffma2(w23, p0, a23[0]);
            a01[1] = ffma2(w01, p1, a01[1]); a23[1] = ffma2(w23, p1, a23[1]);
            a01[2] = ffma2(w01, p2, a01[2]); a23[2] = ffma2(w23, p2, a23[2]);
            a01[3] = ffma2(w01, p3, a01[3]); a23[3] = ffma2(w23, p3, a23[3]);
        }
        __syncthreads();   // everyone done reading old sh2

        float4 h2n;
        {
            float* h2p = (float*)&h2n;
            #pragma unroll
            for (int r = 0; r < 4; r++) {
                float gi, gf, gg, go;
                upk2(a01[r], gi, gf);
                upk2(a23[r], gg, go);
                float cn = sigf(gf) * c2[r] + sigf(gi) * tanhf_(gg);
                c2[r] = cn;
                h2p[r] = sigf(go) * tanhf_(cn);
            }
        }
        sh2[j] = h2n;
        __syncthreads();   // new sh2 visible

        // ---------------- advantage head ----------------------------------
        // hidden[j][r] = relu( sum_k h2[k][r] * adv_w1[j][k] + adv_b1[j] )
        u64 ah01 = pk2(hb, hb);
        u64 ah23 = pk2(hb, hb);
        #pragma unroll 4
        for (int k = 0; k < 256; k++) {
            float  w  = g_advW1t[(k << 8) + j];
            u64    wp = pk2(w, w);
            float4 h4 = sh2[k];
            ah01 = ffma2(wp, pk2(h4.x, h4.y), ah01);
            ah23 = ffma2(wp, pk2(h4.z, h4.w), ah23);
        }
        float hv0, hv1, hv2, hv3;
        upk2(ah01, hv0, hv1);
        upk2(ah23, hv2, hv3);
        float4 part;
        part.x = fmaxf(hv0, 0.f) * w2;
        part.y = fmaxf(hv1, 0.f) * w2;
        part.z = fmaxf(hv2, 0.f) * w2;
        part.w = fmaxf(hv3, 0.f) * w2;

        // block reduction over 256 hidden units
        #pragma unroll
        for (int off = 16; off > 0; off >>= 1) {
            part.x += __shfl_down_sync(0xffffffffu, part.x, off);
            part.y += __shfl_down_sync(0xffffffffu, part.y, off);
            part.z += __shfl_down_sync(0xffffffffu, part.z, off);
            part.w += __shfl_down_sync(0xffffffffu, part.w, off);
        }
        if ((j & 31) == 0) sred[j >> 5] = part;
        __syncthreads();
        if (j < 4) {
            float s = ab2;
            #pragma unroll
            for (int w = 0; w < 8; w++) s += ((const float*)&sred[w])[j];
            g_scores[t * BB + b0 + j] = s;   // time-major flat buffer
        }
        __syncthreads();   // protect sred / shx reuse next step
    }
}

// ---------------------------------------------------------------------------
// softmax over mixed view: row i = g_scores[i*1024 .. i*1024+1023]
// ---------------------------------------------------------------------------
__global__ void __launch_bounds__(256) softmax_kernel(float* __restrict__ out)
{
    __shared__ float sm_m[8];
    __shared__ float sm_s[8];
    const int row = blockIdx.x;
    const int tid = threadIdx.x;
    const float* rp = g_scores + (size_t)row * 1024;

    float v0 = rp[tid], v1 = rp[tid + 256], v2 = rp[tid + 512], v3 = rp[tid + 768];

    float m = fmaxf(fmaxf(v0, v1), fmaxf(v2, v3));
    #pragma unroll
    for (int off = 16; off > 0; off >>= 1)
        m = fmaxf(m, __shfl_xor_sync(0xffffffffu, m, off));
    if ((tid & 31) == 0) sm_m[tid >> 5] = m;
    __syncthreads();
    float bm = sm_m[0];
    #pragma unroll
    for (int w = 1; w < 8; w++) bm = fmaxf(bm, sm_m[w]);

    float e0 = __expf(v0 - bm), e1 = __expf(v1 - bm);
    float e2 = __expf(v2 - bm), e3 = __expf(v3 - bm);
    float s = e0 + e1 + e2 + e3;
    #pragma unroll
    for (int off = 16; off > 0; off >>= 1)
        s += __shfl_xor_sync(0xffffffffu, s, off);
    if ((tid & 31) == 0) sm_s[tid >> 5] = s;
    __syncthreads();
    float S = 0.f;
    #pragma unroll
    for (int w = 0; w < 8; w++) S += sm_s[w];
    float inv = __fdividef(1.0f, S);

    float* op = out + (size_t)row * 1024;
    op[tid]       = e0 * inv;
    op[tid + 256] = e1 * inv;
    op[tid + 512] = e2 * inv;
    op[tid + 768] = e3 * inv;
}

// ---------------------------------------------------------------------------
extern "C" void kernel_launch(void* const* d_in, const int* in_sizes, int n_in,
                              void* d_out, int out_size)
{
    const float* x      = (const float*)d_in[0];
    const float* w_ih0  = (const float*)d_in[1];
    const float* w_hh0  = (const float*)d_in[2];
    const float* b_ih0  = (const float*)d_in[3];
    const float* b_hh0  = (const float*)d_in[4];
    const float* w_ih1  = (const float*)d_in[5];
    const float* w_hh1  = (const float*)d_in[6];
    const float* b_ih1  = (const float*)d_in[7];
    const float* b_hh1  = (const float*)d_in[8];
    const float* adv_w1 = (const float*)d_in[9];
    const float* adv_b1 = (const float*)d_in[10];
    const float* adv_w2 = (const float*)d_in[11];
    const float* adv_b2 = (const float*)d_in[12];
    float* out = (float*)d_out;

    prep_kernel<<<2048, 256>>>(w_ih0, w_hh0, b_ih0, b_hh0,
                               w_ih1, w_hh1, b_ih1, b_hh1, adv_w1);
    lstm_kernel<<<128, 256>>>(x, adv_b1, adv_w2, adv_b2);
    softmax_kernel<<<512, 256>>>(out);
}

// round 3
// speedup vs baseline: 1.5144x; 1.5144x over previous
#include <cuda_runtime.h>
#include <cuda_bf16.h>

// ---------------------------------------------------------------------------
// Policy_LSTM: 2-layer LSTM (B=512, T=1024, H=256, F_IN=10) + MLP head + softmax
//
// Round 2: bf16 weights (fp32 state/accum) -> halve the L2 weight stream,
// row-pair accumulation -> h pairs come straight from LDS.128, no pack movs.
// ---------------------------------------------------------------------------

#define BB 512
#define TT 1024
#define HH 256

// ----- device scratch (static, allocation-free) -----
__device__ __align__(16) unsigned short g_Wbf0h[256 * 1024]; // [k<256][j][q] bf16, w_hh0
__device__ __align__(16) unsigned short g_Wbf1[512 * 1024];  // [k<512][j][q] bf16, [w_ih1; w_hh1]
__device__ __align__(16) float g_Wt0x[10 * 1024];            // [k<10][j][q] fp32, w_ih0
__device__ __align__(16) float g_b0[1024];                   // [j][q] b_ih0+b_hh0
__device__ __align__(16) float g_b1[1024];                   // [j][q] b_ih1+b_hh1
__device__ __align__(16) unsigned short g_advW1bf[256 * 256];// [k][j] bf16 of adv_w1[j][k]
__device__ float g_scores[BB * TT];                          // time-major: idx = t*B + b

// ----- packed f32x2 helpers -----
typedef unsigned long long u64;

__device__ __forceinline__ u64 pk2(float lo, float hi) {
    u64 r;
    asm("mov.b64 %0, {%1, %2};" : "=l"(r) : "f"(lo), "f"(hi));
    return r;
}
__device__ __forceinline__ void upk2(u64 v, float& lo, float& hi) {
    asm("mov.b64 {%0, %1}, %2;" : "=f"(lo), "=f"(hi) : "l"(v));
}
__device__ __forceinline__ u64 ffma2(u64 a, u64 b, u64 c) {
    u64 d;
    asm("fma.rn.f32x2 %0, %1, %2, %3;" : "=l"(d) : "l"(a), "l"(b), "l"(c));
    return d;
}
__device__ __forceinline__ u64 dup2u(unsigned f) {   // f32 bit pattern duplicated
    u64 r;
    asm("mov.b64 %0, {%1, %1};" : "=l"(r) : "r"(f));
    return r;
}
__device__ __forceinline__ u64 dup2f(float f) {
    u64 r;
    asm("mov.b64 %0, {%1, %1};" : "=l"(r) : "f"(f));
    return r;
}

// ----- fast activations (fp32, MUFU based, range-safe) -----
__device__ __forceinline__ float sigf(float v) {
    return __fdividef(1.0f, 1.0f + __expf(-v));
}
__device__ __forceinline__ float tanhf_(float v) {
    v = fminf(fmaxf(v, -15.0f), 15.0f);
    float e = __expf(-2.0f * v);
    return __fdividef(1.0f - e, 1.0f + e);
}

// ---------------------------------------------------------------------------
// prep: repack + bf16-quantize weights (runs every launch; deterministic)
// ---------------------------------------------------------------------------
__global__ void __launch_bounds__(256) prep_kernel(
    const float* __restrict__ w_ih0, const float* __restrict__ w_hh0,
    const float* __restrict__ b_ih0, const float* __restrict__ b_hh0,
    const float* __restrict__ w_ih1, const float* __restrict__ w_hh1,
    const float* __restrict__ b_ih1, const float* __restrict__ b_hh1,
    const float* __restrict__ adv_w1)
{
    int idx = blockIdx.x * blockDim.x + threadIdx.x;
    if (idx >= 512 * 1024) return;

    int k   = idx >> 10;
    int rem = idx & 1023;
    int j   = rem >> 2;
    int q   = rem & 3;
    int g   = q * 256 + j;

    float w1 = (k < 256) ? w_ih1[g * 256 + k] : w_hh1[g * 256 + (k - 256)];
    g_Wbf1[idx] = __bfloat16_as_ushort(__float2bfloat16(w1));

    if (idx < 256 * 1024)
        g_Wbf0h[idx] = __bfloat16_as_ushort(__float2bfloat16(w_hh0[g * 256 + k]));
    if (idx < 10 * 1024)
        g_Wt0x[idx] = w_ih0[g * 10 + k];
    if (idx < 1024) {
        g_b0[idx] = b_ih0[g] + b_hh0[g];
        g_b1[idx] = b_ih1[g] + b_hh1[g];
    }
    if (idx < 256 * 256) {
        int kk = idx >> 8;
        int o  = idx & 255;
        g_advW1bf[idx] = __bfloat16_as_ushort(__float2bfloat16(adv_w1[o * 256 + kk]));
    }
}

// ---------------------------------------------------------------------------
// main recurrence: 128 CTAs, 256 threads, 4 batch rows per CTA
// accumulators are row-pairs: aX01 lanes = (row0, row1), aX23 = (row2, row3)
// ---------------------------------------------------------------------------
__global__ void __launch_bounds__(256) lstm_kernel(
    const float* __restrict__ x,
    const float* __restrict__ adv_b1,
    const float* __restrict__ adv_w2,
    const float* __restrict__ adv_b2)
{
    __shared__ float4 sh1[256];       // h1: [k] -> 4 batch rows
    __shared__ float4 sh2[256];       // h2
    __shared__ float  shx[4][12];     // x_t per batch row (10 used)
    __shared__ float4 sred[8];        // per-warp reduction partials

    const int j  = threadIdx.x;       // hidden unit owned by this thread
    const int b0 = blockIdx.x * 4;    // first batch row of this CTA

    const uint2*  __restrict__ Wb0h = (const uint2*)g_Wbf0h;   // 4 bf16 per (k,j)
    const uint2*  __restrict__ Wb1  = (const uint2*)g_Wbf1;
    const float4* __restrict__ Wt0x = (const float4*)g_Wt0x;
    const unsigned short* __restrict__ AdvW = g_advW1bf;

    const float4 bias0 = ((const float4*)g_b0)[j];   // (i,f,g,o)
    const float4 bias1 = ((const float4*)g_b1)[j];
    const float  hb  = adv_b1[j];
    const float  w2  = adv_w2[j];
    const float  ab2 = adv_b2[0];

    float c1[4] = {0.f, 0.f, 0.f, 0.f};
    float c2[4] = {0.f, 0.f, 0.f, 0.f};
    sh1[j] = make_float4(0.f, 0.f, 0.f, 0.f);
    sh2[j] = make_float4(0.f, 0.f, 0.f, 0.f);
    __syncthreads();

    for (int t = 0; t < TT; t++) {
        // stage x_t for this CTA's 4 batch rows
        if (j < 40) {
            int r = j / 10, cc = j - r * 10;
            shx[r][cc] = x[(size_t)(b0 + r) * (TT * 10) + t * 10 + cc];
        }

        // ---------------- cell 0: gates = b0 + h1 W_hh0^T + x W_ih0^T ------
        u64 aI01, aI23, aF01, aF23, aG01, aG23, aO01, aO23;
        aI01 = aI23 = dup2f(bias0.x);
        aF01 = aF23 = dup2f(bias0.y);
        aG01 = aG23 = dup2f(bias0.z);
        aO01 = aO23 = dup2f(bias0.w);

        #pragma unroll 8
        for (int k = 0; k < 256; k++) {
            uint2 wb = Wb0h[(k << 8) + j];
            ulonglong2 h = *(const ulonglong2*)&sh1[k];
            u64 wi = dup2u(wb.x << 16);
            u64 wf = dup2u(wb.x & 0xffff0000u);
            u64 wg = dup2u(wb.y << 16);
            u64 wo = dup2u(wb.y & 0xffff0000u);
            aI01 = ffma2(wi, h.x, aI01); aI23 = ffma2(wi, h.y, aI23);
            aF01 = ffma2(wf, h.x, aF01); aF23 = ffma2(wf, h.y, aF23);
            aG01 = ffma2(wg, h.x, aG01); aG23 = ffma2(wg, h.y, aG23);
            aO01 = ffma2(wo, h.x, aO01); aO23 = ffma2(wo, h.y, aO23);
        }
        __syncthreads();   // shx visible; everyone done reading old sh1

        #pragma unroll
        for (int k = 0; k < 10; k++) {
            float4 w4 = Wt0x[(k << 8) + j];
            u64 x01 = pk2(shx[0][k], shx[1][k]);
            u64 x23 = pk2(shx[2][k], shx[3][k]);
            u64 wi = dup2f(w4.x), wf = dup2f(w4.y);
            u64 wg = dup2f(w4.z), wo = dup2f(w4.w);
            aI01 = ffma2(wi, x01, aI01); aI23 = ffma2(wi, x23, aI23);
            aF01 = ffma2(wf, x01, aF01); aF23 = ffma2(wf, x23, aF23);
            aG01 = ffma2(wg, x01, aG01); aG23 = ffma2(wg, x23, aG23);
            aO01 = ffma2(wo, x01, aO01); aO23 = ffma2(wo, x23, aO23);
        }

        float4 h1n;
        {
            float gi[4], gf[4], gg[4], go[4];
            upk2(aI01, gi[0], gi[1]); upk2(aI23, gi[2], gi[3]);
            upk2(aF01, gf[0], gf[1]); upk2(aF23, gf[2], gf[3]);
            upk2(aG01, gg[0], gg[1]); upk2(aG23, gg[2], gg[3]);
            upk2(aO01, go[0], go[1]); upk2(aO23, go[2], go[3]);
            float* h1p = (float*)&h1n;
            #pragma unroll
            for (int r = 0; r < 4; r++) {
                float cn = sigf(gf[r]) * c1[r] + sigf(gi[r]) * tanhf_(gg[r]);
                c1[r] = cn;
                h1p[r] = sigf(go[r]) * tanhf_(cn);
            }
        }
        sh1[j] = h1n;        // all reads of old sh1 completed pre-barrier
        __syncthreads();     // new sh1 visible

        // ---------------- cell 1: gates = b1 + h1 W_ih1^T + h2 W_hh1^T -----
        aI01 = aI23 = dup2f(bias1.x);
        aF01 = aF23 = dup2f(bias1.y);
        aG01 = aG23 = dup2f(bias1.z);
        aO01 = aO23 = dup2f(bias1.w);

        #pragma unroll 8
        for (int k = 0; k < 256; k++) {
            uint2 wb = Wb1[(k << 8) + j];
            ulonglong2 h = *(const ulonglong2*)&sh1[k];
            u64 wi = dup2u(wb.x << 16);
            u64 wf = dup2u(wb.x & 0xffff0000u);
            u64 wg = dup2u(wb.y << 16);
            u64 wo = dup2u(wb.y & 0xffff0000u);
            aI01 = ffma2(wi, h.x, aI01); aI23 = ffma2(wi, h.y, aI23);
            aF01 = ffma2(wf, h.x, aF01); aF23 = ffma2(wf, h.y, aF23);
            aG01 = ffma2(wg, h.x, aG01); aG23 = ffma2(wg, h.y, aG23);
            aO01 = ffma2(wo, h.x, aO01); aO23 = ffma2(wo, h.y, aO23);
        }
        #pragma unroll 8
        for (int k = 0; k < 256; k++) {
            uint2 wb = Wb1[((k + 256) << 8) + j];
            ulonglong2 h = *(const ulonglong2*)&sh2[k];
            u64 wi = dup2u(wb.x << 16);
            u64 wf = dup2u(wb.x & 0xffff0000u);
            u64 wg = dup2u(wb.y << 16);
            u64 wo = dup2u(wb.y & 0xffff0000u);
            aI01 = ffma2(wi, h.x, aI01); aI23 = ffma2(wi, h.y, aI23);
            aF01 = ffma2(wf, h.x, aF01); aF23 = ffma2(wf, h.y, aF23);
            aG01 = ffma2(wg, h.x, aG01); aG23 = ffma2(wg, h.y, aG23);
            aO01 = ffma2(wo, h.x, aO01); aO23 = ffma2(wo, h.y, aO23);
        }
        __syncthreads();   // everyone done reading old sh2

        float4 h2n;
        {
            float gi[4], gf[4], gg[4], go[4];
            upk2(aI01, gi[0], gi[1]); upk2(aI23, gi[2], gi[3]);
            upk2(aF01, gf[0], gf[1]); upk2(aF23, gf[2], gf[3]);
            upk2(aG01, gg[0], gg[1]); upk2(aG23, gg[2], gg[3]);
            upk2(aO01, go[0], go[1]); upk2(aO23, go[2], go[3]);
            float* h2p = (float*)&h2n;
            #pragma unroll
            for (int r = 0; r < 4; r++) {
                float cn = sigf(gf[r]) * c2[r] + sigf(gi[r]) * tanhf_(gg[r]);
                c2[r] = cn;
                h2p[r] = sigf(go[r]) * tanhf_(cn);
            }
        }
        sh2[j] = h2n;
        __syncthreads();   // new sh2 visible

        // ---------------- advantage head ----------------------------------
        u64 ah01 = dup2f(hb);
        u64 ah23 = dup2f(hb);
        #pragma unroll 8
        for (int k = 0; k < 256; k++) {
            unsigned u = AdvW[(k << 8) + j];
            ulonglong2 h = *(const ulonglong2*)&sh2[k];
            u64 wp = dup2u(u << 16);
            ah01 = ffma2(wp, h.x, ah01);
            ah23 = ffma2(wp, h.y, ah23);
        }
        float hv0, hv1, hv2, hv3;
        upk2(ah01, hv0, hv1);
        upk2(ah23, hv2, hv3);
        float4 part;
        part.x = fmaxf(hv0, 0.f) * w2;
        part.y = fmaxf(hv1, 0.f) * w2;
        part.z = fmaxf(hv2, 0.f) * w2;
        part.w = fmaxf(hv3, 0.f) * w2;

        #pragma unroll
        for (int off = 16; off > 0; off >>= 1) {
            part.x += __shfl_down_sync(0xffffffffu, part.x, off);
            part.y += __shfl_down_sync(0xffffffffu, part.y, off);
            part.z += __shfl_down_sync(0xffffffffu, part.z, off);
            part.w += __shfl_down_sync(0xffffffffu, part.w, off);
        }
        if ((j & 31) == 0) sred[j >> 5] = part;
        __syncthreads();
        if (j < 4) {
            float s = ab2;
            #pragma unroll
            for (int w = 0; w < 8; w++) s += ((const float*)&sred[w])[j];
            g_scores[t * BB + b0 + j] = s;   // time-major flat buffer
        }
        __syncthreads();   // protect sred / shx reuse next step
    }
}

// ---------------------------------------------------------------------------
// softmax over mixed view: row i = g_scores[i*1024 .. i*1024+1023]
// ---------------------------------------------------------------------------
__global__ void __launch_bounds__(256) softmax_kernel(float* __restrict__ out)
{
    __shared__ float sm_m[8];
    __shared__ float sm_s[8];
    const int row = blockIdx.x;
    const int tid = threadIdx.x;
    const float* rp = g_scores + (size_t)row * 1024;

    float v0 = rp[tid], v1 = rp[tid + 256], v2 = rp[tid + 512], v3 = rp[tid + 768];

    float m = fmaxf(fmaxf(v0, v1), fmaxf(v2, v3));
    #pragma unroll
    for (int off = 16; off > 0; off >>= 1)
        m = fmaxf(m, __shfl_xor_sync(0xffffffffu, m, off));
    if ((tid & 31) == 0) sm_m[tid >> 5] = m;
    __syncthreads();
    float bm = sm_m[0];
    #pragma unroll
    for (int w = 1; w < 8; w++) bm = fmaxf(bm, sm_m[w]);

    float e0 = __expf(v0 - bm), e1 = __expf(v1 - bm);
    float e2 = __expf(v2 - bm), e3 = __expf(v3 - bm);
    float s = e0 + e1 + e2 + e3;
    #pragma unroll
    for (int off = 16; off > 0; off >>= 1)
        s += __shfl_xor_sync(0xffffffffu, s, off);
    if ((tid & 31) == 0) sm_s[tid >> 5] = s;
    __syncthreads();
    float S = 0.f;
    #pragma unroll
    for (int w = 0; w < 8; w++) S += sm_s[w];
    float inv = __fdividef(1.0f, S);

    float* op = out + (size_t)row * 1024;
    op[tid]       = e0 * inv;
    op[tid + 256] = e1 * inv;
    op[tid + 512] = e2 * inv;
    op[tid + 768] = e3 * inv;
}

// ---------------------------------------------------------------------------
extern "C" void kernel_launch(void* const* d_in, const int* in_sizes, int n_in,
                              void* d_out, int out_size)
{
    const float* x      = (const float*)d_in[0];
    const float* w_ih0  = (const float*)d_in[1];
    const float* w_hh0  = (const float*)d_in[2];
    const float* b_ih0  = (const float*)d_in[3];
    const float* b_hh0  = (const float*)d_in[4];
    const float* w_ih1  = (const float*)d_in[5];
    const float* w_hh1  = (const float*)d_in[6];
    const float* b_ih1  = (const float*)d_in[7];
    const float* b_hh1  = (const float*)d_in[8];
    const float* adv_w1 = (const float*)d_in[9];
    const float* adv_b1 = (const float*)d_in[10];
    const float* adv_w2 = (const float*)d_in[11];
    const float* adv_b2 = (const float*)d_in[12];
    float* out = (float*)d_out;

    prep_kernel<<<2048, 256>>>(w_ih0, w_hh0, b_ih0, b_hh0,
                               w_ih1, w_hh1, b_ih1, b_hh1, adv_w1);
    lstm_kernel<<<128, 256>>>(x, adv_b1, adv_w2, adv_b2);
    softmax_kernel<<<512, 256>>>(out);
}